// round 8
// baseline (speedup 1.0000x reference)
#include <cuda_runtime.h>

#define BATCHN 256
#define SEQN   1024
#define HIDN   200
#define VOCABN 33

#define NCPG  50            // col groups of 4: 50*4 = 200
#define NCHK  8             // i-chunks of 25
#define NI    25
#define NWRKT 400           // active GEMV workers
#define WARR  416           // worker arrive-group (13 warps)
#define NFIN  64            // finalizer threads (warps 13,14)
#define TPB   480

#define WOPW  36            // padded W_o row (33 -> 36)
#define GTPB  256           // logits GEMM block

// named barrier ids (0 reserved for __syncthreads)
#define BP0 1
#define BP1 2
#define BH0 3
#define BH1 4

__device__ float d_E2[VOCABN * HIDN];
__device__ float d_wop[HIDN * WOPW];
__device__ int   d_x_is32;
__device__ float d_H[(size_t)BATCHN * SEQN * HIDN];   // 210MB scratch

union F2U { unsigned long long u; float2 f2; };

__device__ __forceinline__ void fma2(unsigned long long& d,
                                     unsigned long long a,
                                     unsigned long long b) {
    asm("fma.rn.f32x2 %0, %1, %2, %0;" : "+l"(d) : "l"(a), "l"(b));
}
__device__ __forceinline__ unsigned long long pack2(float x) {
    F2U r; r.f2 = make_float2(x, x); return r.u;
}
__device__ __forceinline__ float fast_tanh(float x) {
    float e = __expf(2.0f * x);
    return 1.0f - __fdividef(2.0f, e + 1.0f);
}
__device__ __forceinline__ void bar_arrive(int id) {
    asm volatile("bar.arrive %0, %1;" :: "r"(id), "r"(TPB) : "memory");
}
__device__ __forceinline__ void bar_sync(int id) {
    asm volatile("bar.sync %0, %1;" :: "r"(id), "r"(TPB) : "memory");
}

// ---------------------------------------------------------------------------
__global__ void prep_kernel(const float* __restrict__ emb,
                            const float* __restrict__ We,
                            const int* __restrict__ x32) {
    int v = blockIdx.x, j = threadIdx.x;
    if (v == 0 && j == 0) {
        int is32 = 0;
        for (int i = 0; i < 128; i++)
            if (x32[2 * i + 1] != 0) is32 = 1;
        d_x_is32 = is32;
    }
    float acc = 0.f;
#pragma unroll 8
    for (int e = 0; e < HIDN; e++)
        acc += emb[v * HIDN + e] * We[e * HIDN + j];
    d_E2[v * HIDN + j] = acc;
}

__global__ void prep2_kernel(const float* __restrict__ Wo) {
    int k = blockIdx.x * blockDim.x + threadIdx.x;
    if (k < HIDN * WOPW) {
        int i = k / WOPW, v = k % WOPW;
        d_wop[k] = (v < VOCABN) ? Wo[i * VOCABN + v] : 0.f;
    }
}

// ---------------------------------------------------------------------------
// Scan: two independent batch rows pipelined at half-step offset.
//   half-step k: workers GEMV row k&1 step k>>1; finalizers finish row (k-1)&1.
// ---------------------------------------------------------------------------
struct __align__(16) Smem {
    unsigned long long hpad[2][NCHK][26];   // {h,h} per col, chunk-padded/aligned
    float  part[2][NCHK][HIDN];             // partials [rowpar][chunk][col]
    float  e2[VOCABN * HIDN];
    int    xi[2][SEQN];
};

extern __shared__ unsigned char smem_raw[];

__global__ void __launch_bounds__(TPB, 1)
scan_kernel(const void* __restrict__ xv,
            const float* __restrict__ hidden,
            const float* __restrict__ Wh,
            float* __restrict__ out_hidden,
            int write_h) {
    Smem& s = *reinterpret_cast<Smem*>(smem_raw);
    const int tid = threadIdx.x;
    const int b0  = blockIdx.x * 2;

    // ---- setup ----
    for (int k = tid; k < VOCABN * HIDN; k += TPB) s.e2[k] = d_E2[k];
    {
        const int is32 = d_x_is32;
        const int* __restrict__ x32 = (const int*)xv;
        const long long* __restrict__ x64 = (const long long*)xv;
        for (int k = tid; k < 2 * SEQN; k += TPB) {
            int r = k >> 10, t = k & (SEQN - 1);
            long long idx = is32 ? (long long)x32[(size_t)(b0 + r) * SEQN + t]
                                 : x64[(size_t)(b0 + r) * SEQN + t];
            s.xi[r][t] = (int)idx;
        }
    }
    for (int k = tid; k < 2 * HIDN; k += TPB) {
        int r = k / HIDN, j = k % HIDN;
        s.hpad[r][j / NI][j % NI] = pack2(hidden[(size_t)(b0 + r) * HIDN + j]);
    }

    if (tid < WARR) {
        // =================== worker group (13 warps) ===================
        const int cpg = tid % NCPG;          // cols 4cpg..4cpg+3
        const int ch  = (tid < NWRKT) ? tid / NCPG : 0;
        const int i0  = ch * NI;
        unsigned long long w0r[NI], w1r[NI];
        if (tid < NWRKT) {
            const float* wp = Wh + (size_t)i0 * HIDN + 4 * cpg;
#pragma unroll
            for (int ii = 0; ii < NI; ii++) {
                w0r[ii] = *reinterpret_cast<const unsigned long long*>(wp + (size_t)ii * HIDN);
                w1r[ii] = *reinterpret_cast<const unsigned long long*>(wp + (size_t)ii * HIDN + 2);
            }
        }
        __syncthreads();

#pragma unroll 1
        for (int k = 0; k < 2 * SEQN; k++) {
            const int par = k & 1;
            if (k >= 2) bar_sync(par ? BH1 : BH0);   // fin(k-2) done
            if (tid < NWRKT) {
                F2U a0, a1;
                a0.u = a1.u = 0ull;
                const ulonglong2* hp =
                    reinterpret_cast<const ulonglong2*>(&s.hpad[par][ch][0]);
#pragma unroll
                for (int q = 0; q < 12; q++) {
                    ulonglong2 hd = hp[q];
                    fma2(a0.u, w0r[2 * q],     hd.x);
                    fma2(a1.u, w1r[2 * q],     hd.x);
                    fma2(a0.u, w0r[2 * q + 1], hd.y);
                    fma2(a1.u, w1r[2 * q + 1], hd.y);
                }
                unsigned long long hl = s.hpad[par][ch][24];
                fma2(a0.u, w0r[24], hl);
                fma2(a1.u, w1r[24], hl);
                *reinterpret_cast<float4*>(&s.part[par][ch][4 * cpg]) =
                    make_float4(a0.f2.x, a0.f2.y, a1.f2.x, a1.f2.y);
            }
            bar_arrive(par ? BP1 : BP0);             // partials(k) ready
        }
        // drain the last two finalize phases
        bar_sync(BH0);
        bar_sync(BH1);
    } else {
        // =================== finalizer group (2 warps) ===================
        const int fid = tid - WARR;                  // 0..63
        __syncthreads();

#pragma unroll 1
        for (int k = 0; k < 2 * SEQN; k++) {
            const int par = k & 1;                   // row
            const int t   = k >> 1;
            bar_sync(par ? BP1 : BP0);               // partials(k) ready
            const int xi = s.xi[par][t];
            const float* pb = &s.part[par][0][0];
            const float* e2r = &s.e2[xi * HIDN];
            float* hout = &d_H[((size_t)(b0 + par) * SEQN + t) * HIDN];
#pragma unroll
            for (int j = fid; j < HIDN; j += NFIN) {
                float sum = 0.f;
#pragma unroll
                for (int c = 0; c < NCHK; c++) sum += pb[c * HIDN + j];
                float h = fast_tanh(sum + e2r[j]);
                s.hpad[par][j / NI][j % NI] = pack2(h);
                hout[j] = h;
                if (write_h && t == SEQN - 1)
                    out_hidden[(size_t)(b0 + par) * HIDN + j] = h;
            }
            bar_arrive(par ? BH1 : BH0);             // h(k) ready
        }
    }
}

// ---------------------------------------------------------------------------
// Logits GEMM (R7 version, unchanged): 1 row/thread, 3 blocks/SM.
// ---------------------------------------------------------------------------
__global__ void __launch_bounds__(GTPB, 3)
logits_kernel(float* __restrict__ out) {
    __shared__ float wop_s[HIDN * WOPW];
    const int tid = threadIdx.x;
    for (int k = tid; k < HIDN * WOPW; k += GTPB) wop_s[k] = d_wop[k];
    __syncthreads();

    const size_t row = (size_t)blockIdx.x * GTPB + tid;

    F2U acc[17];
#pragma unroll
    for (int p = 0; p < 17; p++) acc[p].u = 0ull;

    const float4* hp = reinterpret_cast<const float4*>(&d_H[row * HIDN]);

#pragma unroll 2
    for (int ib = 0; ib < HIDN / 4; ib++) {
        float4 h4 = hp[ib];
        const float he[4] = {h4.x, h4.y, h4.z, h4.w};
#pragma unroll
        for (int e = 0; e < 4; e++) {
            const int i = ib * 4 + e;
            const unsigned long long hd = pack2(he[e]);
            const ulonglong2* wp2 =
                reinterpret_cast<const ulonglong2*>(&wop_s[i * WOPW]);
#pragma unroll
            for (int q = 0; q < 8; q++) {
                ulonglong2 w = wp2[q];
                fma2(acc[2 * q].u,     w.x, hd);
                fma2(acc[2 * q + 1].u, w.y, hd);
            }
            unsigned long long wl =
                *reinterpret_cast<const unsigned long long*>(&wop_s[i * WOPW + 32]);
            fma2(acc[16].u, wl, hd);
        }
    }

    float* o = out + row * VOCABN;
#pragma unroll
    for (int p = 0; p < 16; p++) {
        o[2 * p]     = acc[p].f2.x;
        o[2 * p + 1] = acc[p].f2.y;
    }
    o[32] = acc[16].f2.x;
}

// ---------------------------------------------------------------------------
extern "C" void kernel_launch(void* const* d_in, const int* in_sizes, int n_in,
                              void* d_out, int out_size) {
    const void*  x      = d_in[0];
    const float* hidden = (const float*)d_in[1];
    const float* emb    = (const float*)d_in[2];
    const float* We     = (const float*)d_in[3];
    const float* Wh     = (const float*)d_in[4];
    const float* Wo     = (const float*)d_in[5];

    float* logits = (float*)d_out;
    const long long LOGITS_ELEMS = (long long)BATCHN * SEQN * VOCABN;
    int write_h = (out_size >= (int)(LOGITS_ELEMS + BATCHN * HIDN));
    float* outh = logits + LOGITS_ELEMS;

    prep_kernel<<<VOCABN, HIDN>>>(emb, We, (const int*)x);
    prep2_kernel<<<(HIDN * WOPW + 255) / 256, 256>>>(Wo);

    cudaFuncSetAttribute((const void*)scan_kernel,
                         cudaFuncAttributeMaxDynamicSharedMemorySize,
                         (int)sizeof(Smem));
    scan_kernel<<<BATCHN / 2, TPB, sizeof(Smem)>>>(x, hidden, Wh, outh, write_h);

    logits_kernel<<<(BATCHN * SEQN) / GTPB, GTPB>>>(logits);
}

// round 9
// speedup vs baseline: 1.2886x; 1.2886x over previous
#include <cuda_runtime.h>

#define BATCHN 256
#define SEQN   1024
#define HIDN   200
#define VOCABN 33

#define NCPG  50            // col groups of 4: 50*4 = 200
#define NCHK  10            // i-chunks of 20
#define NI    20
#define NWRK  500
#define TPB   512

#define WOPW  36            // padded W_o row (33 -> 36)
#define GTPB  256           // logits GEMM block

__device__ float d_E2[VOCABN * HIDN];
__device__ float d_wop[HIDN * WOPW];
__device__ int   d_x_is32;
__device__ float d_H[(size_t)BATCHN * SEQN * HIDN];   // 210MB scratch

union F2U { unsigned long long u; float2 f2; };

__device__ __forceinline__ void fma2(unsigned long long& d,
                                     unsigned long long a,
                                     unsigned long long b) {
    asm("fma.rn.f32x2 %0, %1, %2, %0;" : "+l"(d) : "l"(a), "l"(b));
}
__device__ __forceinline__ unsigned long long pack2(float x) {
    F2U r; r.f2 = make_float2(x, x); return r.u;
}
__device__ __forceinline__ float fast_tanh(float x) {
    float e = __expf(2.0f * x);
    return 1.0f - __fdividef(2.0f, e + 1.0f);
}

// ---------------------------------------------------------------------------
__global__ void prep_kernel(const float* __restrict__ emb,
                            const float* __restrict__ We,
                            const int* __restrict__ x32) {
    int v = blockIdx.x, j = threadIdx.x;
    if (v == 0 && j == 0) {
        int is32 = 0;
        for (int i = 0; i < 128; i++)
            if (x32[2 * i + 1] != 0) is32 = 1;
        d_x_is32 = is32;
    }
    float acc = 0.f;
#pragma unroll 8
    for (int e = 0; e < HIDN; e++)
        acc += emb[v * HIDN + e] * We[e * HIDN + j];
    d_E2[v * HIDN + j] = acc;
}

__global__ void prep2_kernel(const float* __restrict__ Wo) {
    int k = blockIdx.x * blockDim.x + threadIdx.x;
    if (k < HIDN * WOPW) {
        int i = k / WOPW, v = k % WOPW;
        d_wop[k] = (v < VOCABN) ? Wo[i * VOCABN + v] : 0.f;
    }
}

// ---------------------------------------------------------------------------
// Scan: recurrence only — EXACT R7 winning form (frozen).
// ---------------------------------------------------------------------------
struct __align__(16) Smem {
    float4 hdup[HIDN];               // {h0,h0,h1,h1} per column
    float4 part[NCHK][2][NCPG];      // GEMV partials
    float  e2[VOCABN * HIDN];
    int    xi[2][SEQN];
};

extern __shared__ unsigned char smem_raw[];

__global__ void __launch_bounds__(TPB, 1)
scan_kernel(const void* __restrict__ xv,
            const float* __restrict__ hidden,
            const float* __restrict__ Wh,
            float* __restrict__ out_hidden,
            int write_h) {
    Smem& s = *reinterpret_cast<Smem*>(smem_raw);
    const int tid = threadIdx.x;
    const int b0  = blockIdx.x * 2;

    for (int k = tid; k < VOCABN * HIDN; k += TPB) s.e2[k] = d_E2[k];
    {
        const int is32 = d_x_is32;
        const int* __restrict__ x32 = (const int*)xv;
        const long long* __restrict__ x64 = (const long long*)xv;
        for (int k = tid; k < 2 * SEQN; k += TPB) {
            int r = k >> 10, t = k & (SEQN - 1);
            long long idx = is32 ? (long long)x32[(size_t)(b0 + r) * SEQN + t]
                                 : x64[(size_t)(b0 + r) * SEQN + t];
            s.xi[r][t] = (int)idx;
        }
    }
    for (int j = tid; j < HIDN; j += TPB) {
        float a = hidden[(size_t)b0 * HIDN + j];
        float b = hidden[(size_t)(b0 + 1) * HIDN + j];
        s.hdup[j] = make_float4(a, a, b, b);
    }

    const int cpg = tid % NCPG;
    const int ch  = tid / NCPG;
    const int i0  = ch * NI;
    unsigned long long w0r[NI], w1r[NI];
    if (tid < NWRK) {
        const float* wp = Wh + (size_t)i0 * HIDN + 4 * cpg;
#pragma unroll
        for (int ii = 0; ii < NI; ii++) {
            w0r[ii] = *reinterpret_cast<const unsigned long long*>(wp + (size_t)ii * HIDN);
            w1r[ii] = *reinterpret_cast<const unsigned long long*>(wp + (size_t)ii * HIDN + 2);
        }
    }

    const int fc = tid % HIDN;
    const int fr = tid / HIDN;

    __syncthreads();

    for (int t = 0; t < SEQN; t++) {
        if (tid < NWRK) {
            F2U a00, a01, a10, a11;
            a00.u = a01.u = a10.u = a11.u = 0ull;
            const ulonglong2* hp =
                reinterpret_cast<const ulonglong2*>(&s.hdup[i0]);
#pragma unroll
            for (int ii = 0; ii < NI; ii++) {
                ulonglong2 hd = hp[ii];
                fma2(a00.u, w0r[ii], hd.x);
                fma2(a01.u, w1r[ii], hd.x);
                fma2(a10.u, w0r[ii], hd.y);
                fma2(a11.u, w1r[ii], hd.y);
            }
            s.part[ch][0][cpg] = make_float4(a00.f2.x, a00.f2.y, a01.f2.x, a01.f2.y);
            s.part[ch][1][cpg] = make_float4(a10.f2.x, a10.f2.y, a11.f2.x, a11.f2.y);
        }
        __syncthreads();

        if (tid < 2 * HIDN) {
            const float* pb = reinterpret_cast<const float*>(s.part);
            float sum = 0.f;
#pragma unroll
            for (int c = 0; c < NCHK; c++)
                sum += pb[((c * 2 + fr) * NCPG + (fc >> 2)) * 4 + (fc & 3)];
            const int xi = s.xi[fr][t];
            float h = fast_tanh(sum + s.e2[xi * HIDN + fc]);
            F2U hh; hh.f2 = make_float2(h, h);
            *reinterpret_cast<unsigned long long*>(
                reinterpret_cast<char*>(&s.hdup[fc]) + fr * 8) = hh.u;
            d_H[((size_t)(b0 + fr) * SEQN + t) * HIDN + fc] = h;
            if (write_h && t == SEQN - 1)
                out_hidden[(size_t)(b0 + fr) * HIDN + fc] = h;
        }
        __syncthreads();
    }
}

// ---------------------------------------------------------------------------
// Logits GEMM v4: 2 rows/thread, 2 blocks/SM, staged LDG for MLP.
// ---------------------------------------------------------------------------
__global__ void __launch_bounds__(GTPB, 2)
logits_kernel(float* __restrict__ out) {
    __shared__ float wop_s[HIDN * WOPW];   // 28.8KB
    const int tid = threadIdx.x;
    for (int k = tid; k < HIDN * WOPW; k += GTPB) wop_s[k] = d_wop[k];
    __syncthreads();

    const size_t row0 = (size_t)blockIdx.x * (2 * GTPB) + tid;
    const size_t row1 = row0 + GTPB;

    F2U acc0[17], acc1[17];
#pragma unroll
    for (int p = 0; p < 17; p++) { acc0[p].u = 0ull; acc1[p].u = 0ull; }

    const float4* h0p = reinterpret_cast<const float4*>(&d_H[row0 * HIDN]);
    const float4* h1p = reinterpret_cast<const float4*>(&d_H[row1 * HIDN]);

#pragma unroll 1
    for (int ob = 0; ob < HIDN / 8; ob++) {
        // stage 4 x LDG.128 (MLP 4)
        float4 ha0 = h0p[2 * ob], hb0 = h0p[2 * ob + 1];
        float4 ha1 = h1p[2 * ob], hb1 = h1p[2 * ob + 1];
        const float e0[8] = {ha0.x, ha0.y, ha0.z, ha0.w, hb0.x, hb0.y, hb0.z, hb0.w};
        const float e1[8] = {ha1.x, ha1.y, ha1.z, ha1.w, hb1.x, hb1.y, hb1.z, hb1.w};
#pragma unroll
        for (int e = 0; e < 8; e++) {
            const int i = ob * 8 + e;
            const unsigned long long hd0 = pack2(e0[e]);
            const unsigned long long hd1 = pack2(e1[e]);
            const ulonglong2* wp2 =
                reinterpret_cast<const ulonglong2*>(&wop_s[i * WOPW]);
#pragma unroll
            for (int q = 0; q < 8; q++) {
                ulonglong2 w = wp2[q];
                fma2(acc0[2 * q].u,     w.x, hd0);
                fma2(acc0[2 * q + 1].u, w.y, hd0);
                fma2(acc1[2 * q].u,     w.x, hd1);
                fma2(acc1[2 * q + 1].u, w.y, hd1);
            }
            unsigned long long wl =
                *reinterpret_cast<const unsigned long long*>(&wop_s[i * WOPW + 32]);
            fma2(acc0[16].u, wl, hd0);
            fma2(acc1[16].u, wl, hd1);
        }
    }

    float* o0 = out + row0 * VOCABN;
    float* o1 = out + row1 * VOCABN;
#pragma unroll
    for (int p = 0; p < 16; p++) {
        o0[2 * p] = acc0[p].f2.x;  o0[2 * p + 1] = acc0[p].f2.y;
        o1[2 * p] = acc1[p].f2.x;  o1[2 * p + 1] = acc1[p].f2.y;
    }
    o0[32] = acc0[16].f2.x;
    o1[32] = acc1[16].f2.x;
}

// ---------------------------------------------------------------------------
extern "C" void kernel_launch(void* const* d_in, const int* in_sizes, int n_in,
                              void* d_out, int out_size) {
    const void*  x      = d_in[0];
    const float* hidden = (const float*)d_in[1];
    const float* emb    = (const float*)d_in[2];
    const float* We     = (const float*)d_in[3];
    const float* Wh     = (const float*)d_in[4];
    const float* Wo     = (const float*)d_in[5];

    float* logits = (float*)d_out;
    const long long LOGITS_ELEMS = (long long)BATCHN * SEQN * VOCABN;
    int write_h = (out_size >= (int)(LOGITS_ELEMS + BATCHN * HIDN));
    float* outh = logits + LOGITS_ELEMS;

    prep_kernel<<<VOCABN, HIDN>>>(emb, We, (const int*)x);
    prep2_kernel<<<(HIDN * WOPW + 255) / 256, 256>>>(Wo);

    cudaFuncSetAttribute((const void*)scan_kernel,
                         cudaFuncAttributeMaxDynamicSharedMemorySize,
                         (int)sizeof(Smem));
    scan_kernel<<<BATCHN / 2, TPB, sizeof(Smem)>>>(x, hidden, Wh, outh, write_h);

    logits_kernel<<<(BATCHN * SEQN) / (2 * GTPB), GTPB>>>(logits);
}

// round 10
// speedup vs baseline: 1.3250x; 1.0283x over previous
#include <cuda_runtime.h>

#define BATCHN 256
#define SEQN   1024
#define HIDN   200
#define VOCABN 33

#define NCPG  50            // col groups of 4: 50*4 = 200
#define NCHK  10            // i-chunks of 20
#define NI    20
#define NWRK  500
#define TPB   512

#define WOPW  36            // padded W_o row (33 -> 36)

__device__ float d_E2[VOCABN * HIDN];
__device__ float d_wop[HIDN * WOPW];
__device__ int   d_x_is32;
__device__ float d_H[(size_t)BATCHN * SEQN * HIDN];   // 210MB scratch

union F2U { unsigned long long u; float2 f2; };

__device__ __forceinline__ void fma2(unsigned long long& d,
                                     unsigned long long a,
                                     unsigned long long b) {
    asm("fma.rn.f32x2 %0, %1, %2, %0;" : "+l"(d) : "l"(a), "l"(b));
}
__device__ __forceinline__ unsigned long long pack2(float x) {
    F2U r; r.f2 = make_float2(x, x); return r.u;
}
__device__ __forceinline__ float fast_tanh(float x) {
    float e = __expf(2.0f * x);
    return 1.0f - __fdividef(2.0f, e + 1.0f);
}

// ---------------------------------------------------------------------------
__global__ void prep_kernel(const float* __restrict__ emb,
                            const float* __restrict__ We,
                            const int* __restrict__ x32) {
    int v = blockIdx.x, j = threadIdx.x;
    if (v == 0 && j == 0) {
        int is32 = 0;
        for (int i = 0; i < 128; i++)
            if (x32[2 * i + 1] != 0) is32 = 1;
        d_x_is32 = is32;
    }
    float acc = 0.f;
#pragma unroll 8
    for (int e = 0; e < HIDN; e++)
        acc += emb[v * HIDN + e] * We[e * HIDN + j];
    d_E2[v * HIDN + j] = acc;
}

__global__ void prep2_kernel(const float* __restrict__ Wo) {
    int k = blockIdx.x * blockDim.x + threadIdx.x;
    if (k < HIDN * WOPW) {
        int i = k / WOPW, v = k % WOPW;
        d_wop[k] = (v < VOCABN) ? Wo[i * VOCABN + v] : 0.f;
    }
}

// ---------------------------------------------------------------------------
// Scan (frozen R7 form) + fused logits tail over this CTA's own 2048 H rows.
// ---------------------------------------------------------------------------
struct __align__(16) Smem {
    float4 hdup[HIDN];               // {h0,h0,h1,h1} per column
    float4 part[NCHK][2][NCPG];      // GEMV partials
    float  e2[VOCABN * HIDN];
    float  wop[HIDN * WOPW];         // padded W_o for the tail
    int    xi[2][SEQN];
};

extern __shared__ unsigned char smem_raw[];

__global__ void __launch_bounds__(TPB, 1)
scan_kernel(const void* __restrict__ xv,
            const float* __restrict__ hidden,
            const float* __restrict__ Wh,
            float* __restrict__ out_logits,
            float* __restrict__ out_hidden,
            int write_h) {
    Smem& s = *reinterpret_cast<Smem*>(smem_raw);
    const int tid = threadIdx.x;
    const int b0  = blockIdx.x * 2;

    // ---- setup ----
    for (int k = tid; k < VOCABN * HIDN; k += TPB) s.e2[k] = d_E2[k];
    for (int k = tid; k < HIDN * WOPW; k += TPB) s.wop[k] = d_wop[k];
    {
        const int is32 = d_x_is32;
        const int* __restrict__ x32 = (const int*)xv;
        const long long* __restrict__ x64 = (const long long*)xv;
        for (int k = tid; k < 2 * SEQN; k += TPB) {
            int r = k >> 10, t = k & (SEQN - 1);
            long long idx = is32 ? (long long)x32[(size_t)(b0 + r) * SEQN + t]
                                 : x64[(size_t)(b0 + r) * SEQN + t];
            s.xi[r][t] = (int)idx;
        }
    }
    for (int j = tid; j < HIDN; j += TPB) {
        float a = hidden[(size_t)b0 * HIDN + j];
        float b = hidden[(size_t)(b0 + 1) * HIDN + j];
        s.hdup[j] = make_float4(a, a, b, b);
    }

    const int cpg = tid % NCPG;
    const int ch  = tid / NCPG;
    const int i0  = ch * NI;
    unsigned long long w0r[NI], w1r[NI];
    if (tid < NWRK) {
        const float* wp = Wh + (size_t)i0 * HIDN + 4 * cpg;
#pragma unroll
        for (int ii = 0; ii < NI; ii++) {
            w0r[ii] = *reinterpret_cast<const unsigned long long*>(wp + (size_t)ii * HIDN);
            w1r[ii] = *reinterpret_cast<const unsigned long long*>(wp + (size_t)ii * HIDN + 2);
        }
    }

    const int fc = tid % HIDN;
    const int fr = tid / HIDN;

    __syncthreads();

    // ================= scan loop (frozen) =================
    for (int t = 0; t < SEQN; t++) {
        if (tid < NWRK) {
            F2U a00, a01, a10, a11;
            a00.u = a01.u = a10.u = a11.u = 0ull;
            const ulonglong2* hp =
                reinterpret_cast<const ulonglong2*>(&s.hdup[i0]);
#pragma unroll
            for (int ii = 0; ii < NI; ii++) {
                ulonglong2 hd = hp[ii];
                fma2(a00.u, w0r[ii], hd.x);
                fma2(a01.u, w1r[ii], hd.x);
                fma2(a10.u, w0r[ii], hd.y);
                fma2(a11.u, w1r[ii], hd.y);
            }
            s.part[ch][0][cpg] = make_float4(a00.f2.x, a00.f2.y, a01.f2.x, a01.f2.y);
            s.part[ch][1][cpg] = make_float4(a10.f2.x, a10.f2.y, a11.f2.x, a11.f2.y);
        }
        __syncthreads();

        if (tid < 2 * HIDN) {
            const float* pb = reinterpret_cast<const float*>(s.part);
            float sum = 0.f;
#pragma unroll
            for (int c = 0; c < NCHK; c++)
                sum += pb[((c * 2 + fr) * NCPG + (fc >> 2)) * 4 + (fc & 3)];
            const int xi = s.xi[fr][t];
            float h = fast_tanh(sum + s.e2[xi * HIDN + fc]);
            F2U hh; hh.f2 = make_float2(h, h);
            *reinterpret_cast<unsigned long long*>(
                reinterpret_cast<char*>(&s.hdup[fc]) + fr * 8) = hh.u;
            d_H[((size_t)(b0 + fr) * SEQN + t) * HIDN + fc] = h;
            if (write_h && t == SEQN - 1)
                out_hidden[(size_t)(b0 + fr) * HIDN + fc] = h;
        }
        __syncthreads();
    }

    // ================= fused logits tail =================
    // This CTA's H rows are global rows [b0*SEQN, (b0+2)*SEQN) — written only
    // by this CTA; __syncthreads() above makes them visible block-wide.
    const float* Hbase = &d_H[(size_t)b0 * SEQN * HIDN];
    float*       Obase = out_logits + (size_t)b0 * SEQN * VOCABN;

#pragma unroll 1
    for (int lr = tid; lr < 2 * SEQN; lr += TPB) {
        const float4* hp = reinterpret_cast<const float4*>(Hbase + (size_t)lr * HIDN);
        F2U acc[17];
#pragma unroll
        for (int p = 0; p < 17; p++) acc[p].u = 0ull;

#pragma unroll 1
        for (int ob = 0; ob < HIDN / 8; ob++) {
            float4 ha = hp[2 * ob];
            float4 hb = hp[2 * ob + 1];
            const float he[8] = {ha.x, ha.y, ha.z, ha.w, hb.x, hb.y, hb.z, hb.w};
#pragma unroll
            for (int e = 0; e < 8; e++) {
                const int i = ob * 8 + e;
                const unsigned long long hd = pack2(he[e]);
                const ulonglong2* wp2 =
                    reinterpret_cast<const ulonglong2*>(&s.wop[i * WOPW]);
#pragma unroll
                for (int q = 0; q < 8; q++) {
                    ulonglong2 w = wp2[q];
                    fma2(acc[2 * q].u,     w.x, hd);
                    fma2(acc[2 * q + 1].u, w.y, hd);
                }
                unsigned long long wl =
                    *reinterpret_cast<const unsigned long long*>(&s.wop[i * WOPW + 32]);
                fma2(acc[16].u, wl, hd);
            }
        }

        float* o = Obase + (size_t)lr * VOCABN;
#pragma unroll
        for (int p = 0; p < 16; p++) {
            o[2 * p]     = acc[p].f2.x;
            o[2 * p + 1] = acc[p].f2.y;
        }
        o[32] = acc[16].f2.x;
    }
}

// ---------------------------------------------------------------------------
extern "C" void kernel_launch(void* const* d_in, const int* in_sizes, int n_in,
                              void* d_out, int out_size) {
    const void*  x      = d_in[0];
    const float* hidden = (const float*)d_in[1];
    const float* emb    = (const float*)d_in[2];
    const float* We     = (const float*)d_in[3];
    const float* Wh     = (const float*)d_in[4];
    const float* Wo     = (const float*)d_in[5];

    float* logits = (float*)d_out;
    const long long LOGITS_ELEMS = (long long)BATCHN * SEQN * VOCABN;
    int write_h = (out_size >= (int)(LOGITS_ELEMS + BATCHN * HIDN));
    float* outh = logits + LOGITS_ELEMS;

    prep_kernel<<<VOCABN, HIDN>>>(emb, We, (const int*)x);
    prep2_kernel<<<(HIDN * WOPW + 255) / 256, 256>>>(Wo);

    cudaFuncSetAttribute((const void*)scan_kernel,
                         cudaFuncAttributeMaxDynamicSharedMemorySize,
                         (int)sizeof(Smem));
    scan_kernel<<<BATCHN / 2, TPB, sizeof(Smem)>>>(
        x, hidden, Wh, logits, outh, write_h);
}

// round 12
// speedup vs baseline: 1.3699x; 1.0339x over previous
#include <cuda_runtime.h>

#define BATCHN 256
#define SEQN   1024
#define HIDN   200
#define VOCABN 33

#define NCPG  50            // col groups of 4: 50*4 = 200
#define NCHK  10            // i-chunks of 20
#define NI    20
#define NWRK  500
#define TPB   512

#define WOPW  36            // padded W_o row (33 -> 36)

__device__ float d_E2[VOCABN * HIDN];
__device__ float d_wop[HIDN * WOPW];
__device__ int   d_x_is32 = 0;      // idempotent atomicOr target
__device__ float d_H[(size_t)BATCHN * SEQN * HIDN];   // 210MB scratch

union F2U { unsigned long long u; float2 f2; };

__device__ __forceinline__ void fma2(unsigned long long& d,
                                     unsigned long long a,
                                     unsigned long long b) {
    asm("fma.rn.f32x2 %0, %1, %2, %0;" : "+l"(d) : "l"(a), "l"(b));
}
__device__ __forceinline__ unsigned long long pack2(float x) {
    F2U r; r.f2 = make_float2(x, x); return r.u;
}
__device__ __forceinline__ float fast_tanh(float x) {
    float e = __expf(2.0f * x);
    return 1.0f - __fdividef(2.0f, e + 1.0f);
}

// ---------------------------------------------------------------------------
__global__ void prep_kernel(const float* __restrict__ emb,
                            const float* __restrict__ We,
                            const int* __restrict__ x32) {
    int v = blockIdx.x, j = threadIdx.x;
    // parallel int32-vs-int64 detection: if x is int64 (nonneg < 33), every
    // odd 32-bit word is 0; sample 128 odd words across 4 warps.
    if (v == 0 && j < 128) {
        unsigned any = __ballot_sync(0xffffffffu, x32[2 * j + 1] != 0);
        if ((j & 31) == 0 && any) atomicOr(&d_x_is32, 1);
    }
    float acc = 0.f;
#pragma unroll 8
    for (int e = 0; e < HIDN; e++)
        acc += emb[v * HIDN + e] * We[e * HIDN + j];
    d_E2[v * HIDN + j] = acc;
}

__global__ void prep2_kernel(const float* __restrict__ Wo) {
    int k = blockIdx.x * blockDim.x + threadIdx.x;
    if (k < HIDN * WOPW) {
        int i = k / WOPW, v = k % WOPW;
        d_wop[k] = (v < VOCABN) ? Wo[i * VOCABN + v] : 0.f;
    }
}

// ---------------------------------------------------------------------------
// Scan (frozen R7 form) + fused logits tail v5b (2-row interleave, reverse,
// scalar logit stores — logit rows are 132B and NOT 8B-aligned).
// ---------------------------------------------------------------------------
struct __align__(16) Smem {
    float4 hdup[HIDN];               // {h0,h0,h1,h1} per column
    float4 part[NCHK][2][NCPG];      // GEMV partials
    float  e2[VOCABN * HIDN];
    float  wop[HIDN * WOPW];         // padded W_o for the tail
    int    xi[2][SEQN];
};

extern __shared__ unsigned char smem_raw[];

__global__ void __launch_bounds__(TPB, 1)
scan_kernel(const void* __restrict__ xv,
            const float* __restrict__ hidden,
            const float* __restrict__ Wh,
            float* __restrict__ out_logits,
            float* __restrict__ out_hidden,
            int write_h) {
    Smem& s = *reinterpret_cast<Smem*>(smem_raw);
    const int tid = threadIdx.x;
    const int b0  = blockIdx.x * 2;

    // ---- setup ----
    for (int k = tid; k < VOCABN * HIDN; k += TPB) s.e2[k] = d_E2[k];
    for (int k = tid; k < HIDN * WOPW; k += TPB) s.wop[k] = d_wop[k];
    {
        const int is32 = d_x_is32;
        const int* __restrict__ x32 = (const int*)xv;
        const long long* __restrict__ x64 = (const long long*)xv;
        for (int k = tid; k < 2 * SEQN; k += TPB) {
            int r = k >> 10, t = k & (SEQN - 1);
            long long idx = is32 ? (long long)x32[(size_t)(b0 + r) * SEQN + t]
                                 : x64[(size_t)(b0 + r) * SEQN + t];
            s.xi[r][t] = (int)idx;
        }
    }
    for (int j = tid; j < HIDN; j += TPB) {
        float a = hidden[(size_t)b0 * HIDN + j];
        float b = hidden[(size_t)(b0 + 1) * HIDN + j];
        s.hdup[j] = make_float4(a, a, b, b);
    }

    const int cpg = tid % NCPG;
    const int ch  = tid / NCPG;
    const int i0  = ch * NI;
    unsigned long long w0r[NI], w1r[NI];
    if (tid < NWRK) {
        const float* wp = Wh + (size_t)i0 * HIDN + 4 * cpg;
#pragma unroll
        for (int ii = 0; ii < NI; ii++) {
            w0r[ii] = *reinterpret_cast<const unsigned long long*>(wp + (size_t)ii * HIDN);
            w1r[ii] = *reinterpret_cast<const unsigned long long*>(wp + (size_t)ii * HIDN + 2);
        }
    }

    const int fc = tid % HIDN;
    const int fr = tid / HIDN;

    __syncthreads();

    // ================= scan loop (frozen) =================
    for (int t = 0; t < SEQN; t++) {
        if (tid < NWRK) {
            F2U a00, a01, a10, a11;
            a00.u = a01.u = a10.u = a11.u = 0ull;
            const ulonglong2* hp =
                reinterpret_cast<const ulonglong2*>(&s.hdup[i0]);
#pragma unroll
            for (int ii = 0; ii < NI; ii++) {
                ulonglong2 hd = hp[ii];
                fma2(a00.u, w0r[ii], hd.x);
                fma2(a01.u, w1r[ii], hd.x);
                fma2(a10.u, w0r[ii], hd.y);
                fma2(a11.u, w1r[ii], hd.y);
            }
            s.part[ch][0][cpg] = make_float4(a00.f2.x, a00.f2.y, a01.f2.x, a01.f2.y);
            s.part[ch][1][cpg] = make_float4(a10.f2.x, a10.f2.y, a11.f2.x, a11.f2.y);
        }
        __syncthreads();

        if (tid < 2 * HIDN) {
            const float* pb = reinterpret_cast<const float*>(s.part);
            float sum = 0.f;
#pragma unroll
            for (int c = 0; c < NCHK; c++)
                sum += pb[((c * 2 + fr) * NCPG + (fc >> 2)) * 4 + (fc & 3)];
            const int xi = s.xi[fr][t];
            float h = fast_tanh(sum + s.e2[xi * HIDN + fc]);
            F2U hh; hh.f2 = make_float2(h, h);
            *reinterpret_cast<unsigned long long*>(
                reinterpret_cast<char*>(&s.hdup[fc]) + fr * 8) = hh.u;
            d_H[((size_t)(b0 + fr) * SEQN + t) * HIDN + fc] = h;
            if (write_h && t == SEQN - 1)
                out_hidden[(size_t)(b0 + fr) * HIDN + fc] = h;
        }
        __syncthreads();
    }

    // ================= fused logits tail v5b =================
    // CTA-private H rows [b0*SEQN, (b0+2)*SEQN); 2 rows interleaved/thread,
    // passes in reverse (recently-written rows first -> L2 hits).
    const float* Hbase = &d_H[(size_t)b0 * SEQN * HIDN];
    float*       Obase = out_logits + (size_t)b0 * SEQN * VOCABN;

#pragma unroll 1
    for (int pass = 1; pass >= 0; pass--) {
        const int rA = pass * 1024 + tid;
        const int rB = rA + 512;
        const float4* hA = reinterpret_cast<const float4*>(Hbase + (size_t)rA * HIDN);
        const float4* hB = reinterpret_cast<const float4*>(Hbase + (size_t)rB * HIDN);

        F2U accA[17], accB[17];
#pragma unroll
        for (int p = 0; p < 17; p++) { accA[p].u = 0ull; accB[p].u = 0ull; }

#pragma unroll 1
        for (int ob = 0; ob < HIDN / 8; ob++) {
            // stage 4 x LDG.128 (both rows) -> MLP 4
            float4 a0 = hA[2 * ob], a1 = hA[2 * ob + 1];
            float4 b0v = hB[2 * ob], b1v = hB[2 * ob + 1];
            const float eA[8] = {a0.x, a0.y, a0.z, a0.w, a1.x, a1.y, a1.z, a1.w};
            const float eB[8] = {b0v.x, b0v.y, b0v.z, b0v.w, b1v.x, b1v.y, b1v.z, b1v.w};
#pragma unroll
            for (int e = 0; e < 8; e++) {
                const int i = ob * 8 + e;
                const unsigned long long hdA = pack2(eA[e]);
                const unsigned long long hdB = pack2(eB[e]);
                const ulonglong2* wp2 =
                    reinterpret_cast<const ulonglong2*>(&s.wop[i * WOPW]);
#pragma unroll
                for (int q = 0; q < 8; q++) {
                    ulonglong2 w = wp2[q];
                    fma2(accA[2 * q].u,     w.x, hdA);
                    fma2(accA[2 * q + 1].u, w.y, hdA);
                    fma2(accB[2 * q].u,     w.x, hdB);
                    fma2(accB[2 * q + 1].u, w.y, hdB);
                }
                unsigned long long wl =
                    *reinterpret_cast<const unsigned long long*>(&s.wop[i * WOPW + 32]);
                fma2(accA[16].u, wl, hdA);
                fma2(accB[16].u, wl, hdB);
            }
        }

        // scalar stores: logit rows are 132 bytes, odd rows not 8B-aligned
        float* oA = Obase + (size_t)rA * VOCABN;
        float* oB = Obase + (size_t)rB * VOCABN;
#pragma unroll
        for (int p = 0; p < 16; p++) {
            oA[2 * p]     = accA[p].f2.x;
            oA[2 * p + 1] = accA[p].f2.y;
            oB[2 * p]     = accB[p].f2.x;
            oB[2 * p + 1] = accB[p].f2.y;
        }
        oA[32] = accA[16].f2.x;
        oB[32] = accB[16].f2.x;
    }
}

// ---------------------------------------------------------------------------
extern "C" void kernel_launch(void* const* d_in, const int* in_sizes, int n_in,
                              void* d_out, int out_size) {
    const void*  x      = d_in[0];
    const float* hidden = (const float*)d_in[1];
    const float* emb    = (const float*)d_in[2];
    const float* We     = (const float*)d_in[3];
    const float* Wh     = (const float*)d_in[4];
    const float* Wo     = (const float*)d_in[5];

    float* logits = (float*)d_out;
    const long long LOGITS_ELEMS = (long long)BATCHN * SEQN * VOCABN;
    int write_h = (out_size >= (int)(LOGITS_ELEMS + BATCHN * HIDN));
    float* outh = logits + LOGITS_ELEMS;

    prep_kernel<<<VOCABN, HIDN>>>(emb, We, (const int*)x);
    prep2_kernel<<<(HIDN * WOPW + 255) / 256, 256>>>(Wo);

    cudaFuncSetAttribute((const void*)scan_kernel,
                         cudaFuncAttributeMaxDynamicSharedMemorySize,
                         (int)sizeof(Smem));
    scan_kernel<<<BATCHN / 2, TPB, sizeof(Smem)>>>(
        x, hidden, Wh, logits, outh, write_h);
}

// round 13
// speedup vs baseline: 1.4131x; 1.0315x over previous
#include <cuda_runtime.h>

#define BATCHN 256
#define SEQN   1024
#define HIDN   200
#define VOCABN 33

#define NCPG  50            // col groups of 4: 50*4 = 200
#define NCHK  10            // i-chunks of 20
#define NI    20
#define NWRK  500
#define TPB   512

#define WOPW  36            // padded W_o row (33 -> 36)
#define NROWS ((size_t)BATCHN * SEQN)   // 262144 global h-rows
#define NOB   (HIDN / 8)    // 25 ob-planes

__device__ float d_E2[VOCABN * HIDN];
__device__ float d_wop[HIDN * WOPW];
__device__ int   d_x_is32 = 0;
// Block-interleaved H: d_H2[(ob*NROWS + globalrow)*8 + lane], 210MB
__device__ float d_H2[(size_t)NOB * NROWS * 8];

union F2U { unsigned long long u; float2 f2; };

__device__ __forceinline__ void fma2(unsigned long long& d,
                                     unsigned long long a,
                                     unsigned long long b) {
    asm("fma.rn.f32x2 %0, %1, %2, %0;" : "+l"(d) : "l"(a), "l"(b));
}
__device__ __forceinline__ unsigned long long pack2(float x) {
    F2U r; r.f2 = make_float2(x, x); return r.u;
}
__device__ __forceinline__ float fast_tanh(float x) {
    float e = __expf(2.0f * x);
    return 1.0f - __fdividef(2.0f, e + 1.0f);
}

// ---------------------------------------------------------------------------
// prep: E2 = emb @ We with We staged in smem (coalesced); is32 detection.
// ---------------------------------------------------------------------------
__global__ void prep_kernel(const float* __restrict__ emb,
                            const float* __restrict__ We,
                            const int* __restrict__ x32) {
    extern __shared__ float psh[];          // [200*200] We + [200] emb row
    float* wsh = psh;
    float* esh = psh + HIDN * HIDN;
    const int v = blockIdx.x, tid = threadIdx.x;

    if (v == 0 && tid < 128) {
        unsigned any = __ballot_sync(0xffffffffu, x32[2 * tid + 1] != 0);
        if ((tid & 31) == 0 && any) atomicOr(&d_x_is32, 1);
    }
    const float4* w4 = reinterpret_cast<const float4*>(We);
    float4* s4 = reinterpret_cast<float4*>(wsh);
    for (int k = tid; k < HIDN * HIDN / 4; k += 256) s4[k] = w4[k];
    for (int k = tid; k < HIDN; k += 256) esh[k] = emb[v * HIDN + k];
    __syncthreads();

    for (int j = tid; j < HIDN; j += 256) {
        float acc = 0.f;
#pragma unroll 8
        for (int e = 0; e < HIDN; e++)
            acc += esh[e] * wsh[e * HIDN + j];
        d_E2[v * HIDN + j] = acc;
    }
}

__global__ void prep2_kernel(const float* __restrict__ Wo) {
    int k = blockIdx.x * blockDim.x + threadIdx.x;
    if (k < HIDN * WOPW) {
        int i = k / WOPW, v = k % WOPW;
        d_wop[k] = (v < VOCABN) ? Wo[i * VOCABN + v] : 0.f;
    }
}

// ---------------------------------------------------------------------------
// Scan (frozen R7 loop) + fused logits tail v6 (coalesced ob-plane H reads).
// ---------------------------------------------------------------------------
struct __align__(16) Smem {
    float4 hdup[HIDN];               // {h0,h0,h1,h1} per column
    float4 part[NCHK][2][NCPG];      // GEMV partials
    float  e2[VOCABN * HIDN];
    float  wop[HIDN * WOPW];         // padded W_o for the tail
    int    xi[2][SEQN];
};

extern __shared__ unsigned char smem_raw[];

__global__ void __launch_bounds__(TPB, 1)
scan_kernel(const void* __restrict__ xv,
            const float* __restrict__ hidden,
            const float* __restrict__ Wh,
            float* __restrict__ out_logits,
            float* __restrict__ out_hidden,
            int write_h) {
    Smem& s = *reinterpret_cast<Smem*>(smem_raw);
    const int tid = threadIdx.x;
    const int b0  = blockIdx.x * 2;

    // ---- setup ----
    for (int k = tid; k < VOCABN * HIDN; k += TPB) s.e2[k] = d_E2[k];
    for (int k = tid; k < HIDN * WOPW; k += TPB) s.wop[k] = d_wop[k];
    {
        const int is32 = d_x_is32;
        const int* __restrict__ x32 = (const int*)xv;
        const long long* __restrict__ x64 = (const long long*)xv;
        for (int k = tid; k < 2 * SEQN; k += TPB) {
            int r = k >> 10, t = k & (SEQN - 1);
            long long idx = is32 ? (long long)x32[(size_t)(b0 + r) * SEQN + t]
                                 : x64[(size_t)(b0 + r) * SEQN + t];
            s.xi[r][t] = (int)idx;
        }
    }
    for (int j = tid; j < HIDN; j += TPB) {
        float a = hidden[(size_t)b0 * HIDN + j];
        float b = hidden[(size_t)(b0 + 1) * HIDN + j];
        s.hdup[j] = make_float4(a, a, b, b);
    }

    const int cpg = tid % NCPG;
    const int ch  = tid / NCPG;
    const int i0  = ch * NI;
    unsigned long long w0r[NI], w1r[NI];
    if (tid < NWRK) {
        const float* wp = Wh + (size_t)i0 * HIDN + 4 * cpg;
#pragma unroll
        for (int ii = 0; ii < NI; ii++) {
            w0r[ii] = *reinterpret_cast<const unsigned long long*>(wp + (size_t)ii * HIDN);
            w1r[ii] = *reinterpret_cast<const unsigned long long*>(wp + (size_t)ii * HIDN + 2);
        }
    }

    const int fc = tid % HIDN;
    const int fr = tid / HIDN;
    const size_t slab = (size_t)b0 << 10;   // b0 * 1024

    __syncthreads();

    // ================= scan loop (frozen) =================
    for (int t = 0; t < SEQN; t++) {
        if (tid < NWRK) {
            F2U a00, a01, a10, a11;
            a00.u = a01.u = a10.u = a11.u = 0ull;
            const ulonglong2* hp =
                reinterpret_cast<const ulonglong2*>(&s.hdup[i0]);
#pragma unroll
            for (int ii = 0; ii < NI; ii++) {
                ulonglong2 hd = hp[ii];
                fma2(a00.u, w0r[ii], hd.x);
                fma2(a01.u, w1r[ii], hd.x);
                fma2(a10.u, w0r[ii], hd.y);
                fma2(a11.u, w1r[ii], hd.y);
            }
            s.part[ch][0][cpg] = make_float4(a00.f2.x, a00.f2.y, a01.f2.x, a01.f2.y);
            s.part[ch][1][cpg] = make_float4(a10.f2.x, a10.f2.y, a11.f2.x, a11.f2.y);
        }
        __syncthreads();

        if (tid < 2 * HIDN) {
            const float* pb = reinterpret_cast<const float*>(s.part);
            float sum = 0.f;
#pragma unroll
            for (int c = 0; c < NCHK; c++)
                sum += pb[((c * 2 + fr) * NCPG + (fc >> 2)) * 4 + (fc & 3)];
            const int xi = s.xi[fr][t];
            float h = fast_tanh(sum + s.e2[xi * HIDN + fc]);
            F2U hh; hh.f2 = make_float2(h, h);
            *reinterpret_cast<unsigned long long*>(
                reinterpret_cast<char*>(&s.hdup[fc]) + fr * 8) = hh.u;
            // block-interleaved write: plane fc>>3, row slab + fr*1024 + t
            d_H2[((size_t)(fc >> 3) * NROWS + slab + ((size_t)fr << 10) + t) * 8
                 + (fc & 7)] = h;
            if (write_h && t == SEQN - 1)
                out_hidden[(size_t)(b0 + fr) * HIDN + fc] = h;
        }
        __syncthreads();
    }

    // ================= fused logits tail v6 =================
    // Rows r = fr*1024 + t (0..2047), CTA-private. Coalesced 32B/thread reads
    // from each ob-plane.
    float* Obase = out_logits + (size_t)b0 * SEQN * VOCABN;

#pragma unroll 1
    for (int pass = 1; pass >= 0; pass--) {
        const int rA = pass * 1024 + tid;
        const int rB = rA + 512;

        F2U accA[17], accB[17];
#pragma unroll
        for (int p = 0; p < 17; p++) { accA[p].u = 0ull; accB[p].u = 0ull; }

#pragma unroll 1
        for (int ob = 0; ob < NOB; ob++) {
            const float4* pl = reinterpret_cast<const float4*>(
                &d_H2[((size_t)ob * NROWS + slab) * 8]);
            float4 a0 = pl[2 * rA], a1 = pl[2 * rA + 1];
            float4 c0 = pl[2 * rB], c1 = pl[2 * rB + 1];
            const float eA[8] = {a0.x, a0.y, a0.z, a0.w, a1.x, a1.y, a1.z, a1.w};
            const float eB[8] = {c0.x, c0.y, c0.z, c0.w, c1.x, c1.y, c1.z, c1.w};
#pragma unroll
            for (int e = 0; e < 8; e++) {
                const int i = ob * 8 + e;
                const unsigned long long hdA = pack2(eA[e]);
                const unsigned long long hdB = pack2(eB[e]);
                const ulonglong2* wp2 =
                    reinterpret_cast<const ulonglong2*>(&s.wop[i * WOPW]);
#pragma unroll
                for (int q = 0; q < 8; q++) {
                    ulonglong2 w = wp2[q];
                    fma2(accA[2 * q].u,     w.x, hdA);
                    fma2(accA[2 * q + 1].u, w.y, hdA);
                    fma2(accB[2 * q].u,     w.x, hdB);
                    fma2(accB[2 * q + 1].u, w.y, hdB);
                }
                unsigned long long wl =
                    *reinterpret_cast<const unsigned long long*>(&s.wop[i * WOPW + 32]);
                fma2(accA[16].u, wl, hdA);
                fma2(accB[16].u, wl, hdB);
            }
        }

        // scalar stores: logit rows are 132 bytes, odd rows not 8B-aligned
        float* oA = Obase + (size_t)rA * VOCABN;
        float* oB = Obase + (size_t)rB * VOCABN;
#pragma unroll
        for (int p = 0; p < 16; p++) {
            oA[2 * p]     = accA[p].f2.x;
            oA[2 * p + 1] = accA[p].f2.y;
            oB[2 * p]     = accB[p].f2.x;
            oB[2 * p + 1] = accB[p].f2.y;
        }
        oA[32] = accA[16].f2.x;
        oB[32] = accB[16].f2.x;
    }
}

// ---------------------------------------------------------------------------
extern "C" void kernel_launch(void* const* d_in, const int* in_sizes, int n_in,
                              void* d_out, int out_size) {
    const void*  x      = d_in[0];
    const float* hidden = (const float*)d_in[1];
    const float* emb    = (const float*)d_in[2];
    const float* We     = (const float*)d_in[3];
    const float* Wh     = (const float*)d_in[4];
    const float* Wo     = (const float*)d_in[5];

    float* logits = (float*)d_out;
    const long long LOGITS_ELEMS = (long long)BATCHN * SEQN * VOCABN;
    int write_h = (out_size >= (int)(LOGITS_ELEMS + BATCHN * HIDN));
    float* outh = logits + LOGITS_ELEMS;

    const int prep_smem = (HIDN * HIDN + HIDN) * (int)sizeof(float);
    cudaFuncSetAttribute((const void*)prep_kernel,
                         cudaFuncAttributeMaxDynamicSharedMemorySize, prep_smem);
    prep_kernel<<<VOCABN, 256, prep_smem>>>(emb, We, (const int*)x);
    prep2_kernel<<<(HIDN * WOPW + 255) / 256, 256>>>(Wo);

    cudaFuncSetAttribute((const void*)scan_kernel,
                         cudaFuncAttributeMaxDynamicSharedMemorySize,
                         (int)sizeof(Smem));
    scan_kernel<<<BATCHN / 2, TPB, sizeof(Smem)>>>(
        x, hidden, Wh, logits, outh, write_h);
}